// round 14
// baseline (speedup 1.0000x reference)
#include <cuda_runtime.h>
#include <cstdint>

#define TPB   256
#define M_CTA 256

// ---------------- smem map (bytes) ----------------
// bias/const: b1[64] b2[64] b3[32] K[6] floats
#define OFF_BIAS 0
#define OFF_W1H  1024                    // 4 segs x [64n][64B] int8 q1
#define OFF_W1L  (OFF_W1H + 16384)
#define OFF_W2H  (OFF_W1L + 16384)      // [64n][64B]
#define OFF_W2L  (OFF_W2H + 4096)
#define OFF_W3H  (OFF_W2L + 4096)       // [32n][64B]
#define OFF_W3L  (OFF_W3H + 2048)
#define STAGE_BYTES (OFF_W3L + 2048)    // 46080
#define OFF_X0H  STAGE_BYTES            // X tiles: [256 rows][64B] int8
#define OFF_X0L  (OFF_X0H + 16384)
#define OFF_X1H  (OFF_X0L + 16384)
#define OFF_X1L  (OFF_X1H + 16384)
#define OFF_HH   (OFF_X1L + 16384)      // h tile (warp-private rows)
#define OFF_HL   (OFF_HH + 16384)
#define SMEM_TOTAL (OFF_HL + 16384)     // 144384

// 64B-row swizzle: XOR 16B-column bits[4:6) with (row>>1)&3  (row = bo>>6)
#define SWZ64(bo) ((bo) ^ ((((bo) >> 7) & 3) << 4))

__device__ __align__(1024) unsigned char g_stage[STAGE_BYTES];
__device__ int g_is64;
__device__ int g_sWbits[3];

// ---------------- PTX wrappers ----------------
__device__ __forceinline__ uint32_t smem_u32(const void* p) {
    uint32_t a;
    asm("{ .reg .u64 t; cvta.to.shared.u64 t, %1; cvt.u32.u64 %0, t; }" : "=r"(a) : "l"(p));
    return a;
}
__device__ __forceinline__ void ldsm4(uint32_t r[4], uint32_t a) {
    asm volatile("ldmatrix.sync.aligned.m8n8.x4.shared.b16 {%0,%1,%2,%3}, [%4];"
        : "=r"(r[0]), "=r"(r[1]), "=r"(r[2]), "=r"(r[3]) : "r"(a));
}
__device__ __forceinline__ void mma_s8(int c[4], const uint32_t a[4], const uint32_t b[2]) {
    asm volatile("mma.sync.aligned.m16n8k32.row.col.s32.s8.s8.s32 "
        "{%0,%1,%2,%3}, {%4,%5,%6,%7}, {%8,%9}, {%0,%1,%2,%3};"
        : "+r"(c[0]), "+r"(c[1]), "+r"(c[2]), "+r"(c[3])
        : "r"(a[0]), "r"(a[1]), "r"(a[2]), "r"(a[3]), "r"(b[0]), "r"(b[1]));
}

// ---------------- numeric helpers ----------------
__device__ __forceinline__ float softplus_f(float v) {
    return fmaxf(v, 0.0f) + __logf(1.0f + __expf(-fabsf(v)));
}
// quantize x (|x|<=8) to q1,q2 int8 pair: x ~= (8/127)*(q1 + q2/128)
__device__ __forceinline__ void quant2(float x, int& q1, int& q2) {
    x = fminf(fmaxf(x, -8.0f), 8.0f);
    q1 = __float2int_rn(x * 15.875f);
    q2 = __float2int_rn(fmaf(x, 2032.0f, -(float)(q1 << 7)));
}
__device__ __forceinline__ uint32_t pack4(int a, int b, int c, int d) {
    uint32_t p01 = __byte_perm((uint32_t)a, (uint32_t)b, 0x0040);
    uint32_t p23 = __byte_perm((uint32_t)c, (uint32_t)d, 0x0040);
    return __byte_perm(p01, p23, 0x5410);
}

// ---------------------------------------------------------------------------
// pass 1: per-tensor weight |max| scales + index-dtype detection
__global__ void stage_scales(const float* __restrict__ W1, const float* __restrict__ W2,
                             const float* __restrict__ W3,
                             const unsigned int* __restrict__ idxprobe) {
    __shared__ int red[3];
    if (threadIdx.x < 3) red[threadIdx.x] = 0;
    __syncthreads();
    if (threadIdx.x < 32) {
        unsigned ok = __ballot_sync(0xFFFFFFFFu, idxprobe[2 * threadIdx.x + 1] == 0u);
        if (threadIdx.x == 0) g_is64 = (ok == 0xFFFFFFFFu);
    }
    float m1 = 0.f, m2 = 0.f, m3 = 0.f;
    for (int i = threadIdx.x; i < 16384; i += 256) m1 = fmaxf(m1, fabsf(W1[i]));
    for (int i = threadIdx.x; i < 4096;  i += 256) m2 = fmaxf(m2, fabsf(W2[i]));
    for (int i = threadIdx.x; i < 2048;  i += 256) m3 = fmaxf(m3, fabsf(W3[i]));
    atomicMax(&red[0], __float_as_int(m1));
    atomicMax(&red[1], __float_as_int(m2));
    atomicMax(&red[2], __float_as_int(m3));
    __syncthreads();
    if (threadIdx.x < 3) g_sWbits[threadIdx.x] = red[threadIdx.x];
}

// pass 2: quantize weights (dual-level int8) + biases + epilogue constants
__global__ void stage_quant(const float* __restrict__ W1, const float* __restrict__ b1,
                            const float* __restrict__ W2, const float* __restrict__ b2,
                            const float* __restrict__ W3, const float* __restrict__ b3) {
    const float sW1 = __int_as_float(g_sWbits[0]);
    const float sW2 = __int_as_float(g_sWbits[1]);
    const float sW3 = __int_as_float(g_sWbits[2]);
    int t = blockIdx.x * blockDim.x + threadIdx.x;
    unsigned char* st = g_stage;
    if (t < 16384) {                       // W1 src [256k][64n]
        int n = t & 63, k = t >> 6;
        int s = k >> 6, kl = k & 63;
        float w = W1[t];
        int q1 = __float2int_rn(w * (127.0f / sW1));
        int q2 = __float2int_rn(fmaf(w, 16256.0f / sW1, -(float)(q1 << 7)));
        uint32_t bo = SWZ64((uint32_t)(n * 64 + kl));
        st[OFF_W1H + s * 4096 + bo] = (unsigned char)(q1 & 0xff);
        st[OFF_W1L + s * 4096 + bo] = (unsigned char)(q2 & 0xff);
    } else if (t < 20480) {                // W2 src [64k][64n]
        int i = t - 16384;
        int n = i & 63, k = i >> 6;
        float w = W2[i];
        int q1 = __float2int_rn(w * (127.0f / sW2));
        int q2 = __float2int_rn(fmaf(w, 16256.0f / sW2, -(float)(q1 << 7)));
        uint32_t bo = SWZ64((uint32_t)(n * 64 + k));
        st[OFF_W2H + bo] = (unsigned char)(q1 & 0xff);
        st[OFF_W2L + bo] = (unsigned char)(q2 & 0xff);
    } else if (t < 22528) {                // W3 src [64k][32n]
        int i = t - 20480;
        int n = i & 31, k = i >> 5;
        float w = W3[k * 32 + n];
        int q1 = __float2int_rn(w * (127.0f / sW3));
        int q2 = __float2int_rn(fmaf(w, 16256.0f / sW3, -(float)(q1 << 7)));
        uint32_t bo = SWZ64((uint32_t)(n * 64 + k));
        st[OFF_W3H + bo] = (unsigned char)(q1 & 0xff);
        st[OFF_W3L + bo] = (unsigned char)(q2 & 0xff);
    } else if (t < 22528 + 64) {
        ((float*)(st + OFF_BIAS))[t - 22528] = b1[t - 22528];
    } else if (t < 22528 + 128) {
        ((float*)(st + OFF_BIAS))[t - 22528] = b2[t - 22592];
    } else if (t < 22528 + 160) {
        ((float*)(st + OFF_BIAS))[t - 22528] = b3[t - 22656];
    } else if (t < 22528 + 166) {
        int j = t - 22688;                 // 160..165
        float s = (j < 2) ? sW1 : (j < 4) ? sW2 : sW3;
        float Kp = 8.0f * s / 16129.0f;    // 127*127
        ((float*)(st + OFF_BIAS))[160 + j] = (j & 1) ? Kp * 0.0078125f : Kp;
    }
}

// ---------------- cooperative gather ----------------
struct GatherCtx {
    const float* bond; const float* atom; const float* glob;
    const void* aidx; const void* gidx;
    int n_bond; int is64; int lb; int part;
};

template<int SEG>
__device__ __forceinline__ void load_chunk(const GatherCtx& c, long long base,
                                           int r0, float4 v[8]) {
    #pragma unroll
    for (int i = 0; i < 8; i++) {
        const int bl = (r0 + i) * 16 + c.lb;
        const long long gb = base + bl;
        const size_t bond = (size_t)((gb < c.n_bond) ? gb : (c.n_bond - 1));
        size_t row; const float* bp;
        if (SEG == 0) { row = bond; bp = c.bond; }
        else if (SEG == 3) {
            row = c.is64 ? (size_t)((const long long*)c.gidx)[bond]
                         : (size_t)((const int*)c.gidx)[bond];
            bp = c.glob;
        } else {
            row = c.is64 ? (size_t)((const long long*)c.aidx)[2 * bond + (SEG - 1)]
                         : (size_t)((const int*)c.aidx)[2 * bond + (SEG - 1)];
            bp = c.atom;
        }
        v[i] = ((const float4*)(bp + row * 64))[c.part];
    }
}

__device__ __forceinline__ void sts_chunk(char* smem, uint32_t offH, uint32_t offL,
                                          int lb, int part, int r0, const float4 v[8]) {
    #pragma unroll
    for (int i = 0; i < 8; i++) {
        const int bl = (r0 + i) * 16 + lb;
        int a1, a2, b1, b2, c1, c2, d1, d2;
        quant2(v[i].x, a1, a2); quant2(v[i].y, b1, b2);
        quant2(v[i].z, c1, c2); quant2(v[i].w, d1, d2);
        const uint32_t bo = SWZ64((uint32_t)(bl * 64 + part * 4));
        *(uint32_t*)(smem + offH + bo) = pack4(a1, b1, c1, d1);
        *(uint32_t*)(smem + offL + bo) = pack4(a2, b2, c2, d2);
    }
}

// ---------------- warp-level s8 GEMM (M=32): kt in [KT0, KT1), k32 each -----
template<int NT, int KT0, int KT1>
__device__ __forceinline__ void gemm_s8(uint32_t sb,
                                        uint32_t offAH, uint32_t offAL,
                                        uint32_t offBH, uint32_t offBL,
                                        int m0, int lane,
                                        int accP[][4], int accQ[][4]) {
    const int ar  = (lane & 15);
    const int akh = ((lane >> 4) << 4);
    const int br  = ((lane >> 4) << 3) + (lane & 7);
    const int bkh = (((lane >> 3) & 1) << 4);
    #pragma unroll
    for (int kt = KT0; kt < KT1; kt++) {
        uint32_t ah[2][4], al[2][4];
        #pragma unroll
        for (int mt = 0; mt < 2; mt++) {
            uint32_t bo = SWZ64((uint32_t)((m0 + mt * 16 + ar) * 64 + kt * 32 + akh));
            ldsm4(ah[mt], sb + offAH + bo);
            ldsm4(al[mt], sb + offAL + bo);
        }
        #pragma unroll
        for (int nb = 0; nb < NT / 2; nb++) {
            uint32_t bo = SWZ64((uint32_t)((nb * 16 + br) * 64 + kt * 32 + bkh));
            uint32_t bh[4], bl[4];
            ldsm4(bh, sb + offBH + bo);
            ldsm4(bl, sb + offBL + bo);
            #pragma unroll
            for (int h2 = 0; h2 < 2; h2++) {
                const uint32_t bfh[2] = { bh[2 * h2], bh[2 * h2 + 1] };
                const uint32_t bfl[2] = { bl[2 * h2], bl[2 * h2 + 1] };
                const int nt = nb * 2 + h2;
                #pragma unroll
                for (int mt = 0; mt < 2; mt++) {
                    mma_s8(accP[mt * NT + nt], ah[mt], bfh);
                    mma_s8(accQ[mt * NT + nt], ah[mt], bfl);
                    mma_s8(accQ[mt * NT + nt], al[mt], bfh);
                }
            }
        }
    }
}

// ---------------- epilogue: combine + bias + softplus + requantize -> H ------
__device__ __forceinline__ void epi_h(char* smem, const float* bias,
                                      float Kp, float Kq, int m0, int lane,
                                      int accP[][4], int accQ[][4]) {
    #pragma unroll
    for (int i = 0; i < 16; i++) {
        const int col = (i & 7) * 8 + (lane & 3) * 2;
        const int rb  = m0 + (i >> 3) * 16 + (lane >> 2);
        const float b0 = bias[col], b1 = bias[col + 1];
        #pragma unroll
        for (int h = 0; h < 2; h++) {
            const int r = rb + h * 8;
            float v0 = softplus_f(fmaf((float)accQ[i][2*h],   Kq, fmaf((float)accP[i][2*h],   Kp, b0)));
            float v1 = softplus_f(fmaf((float)accQ[i][2*h+1], Kq, fmaf((float)accP[i][2*h+1], Kp, b1)));
            int q1a, q2a, q1b, q2b;
            quant2(v0, q1a, q2a); quant2(v1, q1b, q2b);
            const uint32_t bo = SWZ64((uint32_t)(r * 64 + col));
            *(unsigned short*)(smem + OFF_HH + bo) =
                (unsigned short)((q1a & 0xff) | ((q1b & 0xff) << 8));
            *(unsigned short*)(smem + OFF_HL + bo) =
                (unsigned short)((q2a & 0xff) | ((q2b & 0xff) << 8));
        }
    }
}

// ---------------------------------------------------------------------------
__global__ __launch_bounds__(TPB, 1)
void bond_mlp_s8(const float* __restrict__ bond_feats,
                 const float* __restrict__ atom_feats,
                 const float* __restrict__ global_feats,
                 const void*  __restrict__ atom_idx,
                 const void*  __restrict__ global_idx,
                 float* __restrict__ out, int n_bond)
{
    extern __shared__ char smem[];
    const uint32_t sb = smem_u32(smem);
    const int tid  = threadIdx.x;
    const int wid  = tid >> 5;
    const int lane = tid & 31;
    const int m0   = wid * 32;

    GatherCtx ctx;
    ctx.bond = bond_feats; ctx.atom = atom_feats; ctx.glob = global_feats;
    ctx.aidx = atom_idx;   ctx.gidx = global_idx;
    ctx.n_bond = n_bond;   ctx.is64 = g_is64;
    ctx.lb = tid >> 4;     ctx.part = tid & 15;

    const long long ntiles = (n_bond + M_CTA - 1) / M_CTA;
    long long tile = blockIdx.x;
    long long base = tile * M_CTA;

    float4 v[8];

    // prologue: seg0 of first tile LDGs in flight during the weight-image copy
    load_chunk<0>(ctx, base, 0, v);
    {
        const float4* src = (const float4*)g_stage;
        float4* dst = (float4*)smem;
        #pragma unroll 4
        for (int i = tid; i < STAGE_BYTES / 16; i += TPB) dst[i] = src[i];
    }
    sts_chunk(smem, OFF_X0H, OFF_X0L, ctx.lb, ctx.part, 0, v);
    load_chunk<0>(ctx, base, 8, v);
    sts_chunk(smem, OFF_X0H, OFF_X0L, ctx.lb, ctx.part, 8, v);
    __syncthreads();

    const float* bias = (const float*)(smem + OFF_BIAS);

    // persistent tile loop; invariant: X0 holds seg0 of `tile`, synced
    #pragma unroll 1
    while (true) {
        const long long ntile = tile + gridDim.x;
        const bool more = (ntile < ntiles);
        const long long nbase = ntile * M_CTA;

        int accP[16][4], accQ[16][4];
        #pragma unroll
        for (int i = 0; i < 16; i++)
            #pragma unroll
            for (int q = 0; q < 4; q++) { accP[i][q] = 0; accQ[i][q] = 0; }

        // ---- L1 seg0 (X0) | prefetch seg1 -> X1 ----
        load_chunk<1>(ctx, base, 0, v);
        gemm_s8<8, 0, 1>(sb, OFF_X0H, OFF_X0L, OFF_W1H,        OFF_W1L,        m0, lane, accP, accQ);
        sts_chunk(smem, OFF_X1H, OFF_X1L, ctx.lb, ctx.part, 0, v);
        load_chunk<1>(ctx, base, 8, v);
        gemm_s8<8, 1, 2>(sb, OFF_X0H, OFF_X0L, OFF_W1H,        OFF_W1L,        m0, lane, accP, accQ);
        sts_chunk(smem, OFF_X1H, OFF_X1L, ctx.lb, ctx.part, 8, v);
        __syncthreads();

        // ---- seg1 (X1) | prefetch seg2 -> X0 ----
        load_chunk<2>(ctx, base, 0, v);
        gemm_s8<8, 0, 1>(sb, OFF_X1H, OFF_X1L, OFF_W1H + 4096, OFF_W1L + 4096, m0, lane, accP, accQ);
        sts_chunk(smem, OFF_X0H, OFF_X0L, ctx.lb, ctx.part, 0, v);
        load_chunk<2>(ctx, base, 8, v);
        gemm_s8<8, 1, 2>(sb, OFF_X1H, OFF_X1L, OFF_W1H + 4096, OFF_W1L + 4096, m0, lane, accP, accQ);
        sts_chunk(smem, OFF_X0H, OFF_X0L, ctx.lb, ctx.part, 8, v);
        __syncthreads();

        // ---- seg2 (X0) | prefetch seg3 -> X1 ----
        load_chunk<3>(ctx, base, 0, v);
        gemm_s8<8, 0, 1>(sb, OFF_X0H, OFF_X0L, OFF_W1H + 8192, OFF_W1L + 8192, m0, lane, accP, accQ);
        sts_chunk(smem, OFF_X1H, OFF_X1L, ctx.lb, ctx.part, 0, v);
        load_chunk<3>(ctx, base, 8, v);
        gemm_s8<8, 1, 2>(sb, OFF_X0H, OFF_X0L, OFF_W1H + 8192, OFF_W1L + 8192, m0, lane, accP, accQ);
        sts_chunk(smem, OFF_X1H, OFF_X1L, ctx.lb, ctx.part, 8, v);
        __syncthreads();

        // ---- seg3 (X1) ----
        gemm_s8<8, 0, 2>(sb, OFF_X1H, OFF_X1L, OFF_W1H + 12288, OFF_W1L + 12288, m0, lane, accP, accQ);

        // ---- h1 -> H (warp-private rows; warp-level sync only) ----
        epi_h(smem, bias, bias[160], bias[161], m0, lane, accP, accQ);
        __syncwarp();

        // ---- L2 (A from H, B=W2) | prefetch next tile seg0 -> X0 ----
        #pragma unroll
        for (int i = 0; i < 16; i++)
            #pragma unroll
            for (int q = 0; q < 4; q++) { accP[i][q] = 0; accQ[i][q] = 0; }

        if (more) load_chunk<0>(ctx, nbase, 0, v);
        gemm_s8<8, 0, 1>(sb, OFF_HH, OFF_HL, OFF_W2H, OFF_W2L, m0, lane, accP, accQ);
        if (more) { sts_chunk(smem, OFF_X0H, OFF_X0L, ctx.lb, ctx.part, 0, v);
                    load_chunk<0>(ctx, nbase, 8, v); }
        gemm_s8<8, 1, 2>(sb, OFF_HH, OFF_HL, OFF_W2H, OFF_W2L, m0, lane, accP, accQ);
        if (more) sts_chunk(smem, OFF_X0H, OFF_X0L, ctx.lb, ctx.part, 8, v);

        // ---- h2 -> H (overwrite; own rows, after own L2 reads) ----
        __syncwarp();
        epi_h(smem, bias + 64, bias[162], bias[163], m0, lane, accP, accQ);
        __syncwarp();

        // ---- L3 (A from H, B=W3, N=32) ----
        int acc3P[8][4], acc3Q[8][4];
        #pragma unroll
        for (int i = 0; i < 8; i++)
            #pragma unroll
            for (int q = 0; q < 4; q++) { acc3P[i][q] = 0; acc3Q[i][q] = 0; }
        gemm_s8<4, 0, 2>(sb, OFF_HH, OFF_HL, OFF_W3H, OFF_W3L, m0, lane, acc3P, acc3Q);

        // ---- output ----
        {
            const float Kp = bias[164], Kq = bias[165];
            const float* b3s = bias + 128;
            #pragma unroll
            for (int mt = 0; mt < 2; mt++)
            #pragma unroll
            for (int nt = 0; nt < 4; nt++) {
                const int i = mt * 4 + nt;
                const int col = nt * 8 + (lane & 3) * 2;
                const float bv0 = b3s[col], bv1 = b3s[col + 1];
                #pragma unroll
                for (int h = 0; h < 2; h++) {
                    const int row = m0 + mt * 16 + (lane >> 2) + h * 8;
                    const long long gb = base + row;
                    if (gb < n_bond) {
                        float o0 = fmaf((float)acc3Q[i][2*h],   Kq, fmaf((float)acc3P[i][2*h],   Kp, bv0));
                        float o1 = fmaf((float)acc3Q[i][2*h+1], Kq, fmaf((float)acc3P[i][2*h+1], Kp, bv1));
                        *(float2*)(out + (size_t)gb * 32 + col) = make_float2(o0, o1);
                    }
                }
            }
        }

        if (!more) break;
        __syncthreads();   // X0 (next seg0) visible; X1 reads complete
        tile = ntile; base = nbase;
    }
}

// ---------------------------------------------------------------------------
extern "C" void kernel_launch(void* const* d_in, const int* in_sizes, int n_in,
                              void* d_out, int out_size)
{
    const float* bond_feats   = (const float*)d_in[0];
    const float* atom_feats   = (const float*)d_in[1];
    const float* global_feats = (const float*)d_in[2];
    const void*  atom_idx     = d_in[3];
    const void*  global_idx   = d_in[4];
    const float* W1 = (const float*)d_in[5];
    const float* b1 = (const float*)d_in[6];
    const float* W2 = (const float*)d_in[7];
    const float* b2 = (const float*)d_in[8];
    const float* W3 = (const float*)d_in[9];
    const float* b3 = (const float*)d_in[10];
    float* out = (float*)d_out;

    const int n_bond = in_sizes[0] / 64;
    const long long ntiles = (n_bond + M_CTA - 1) / M_CTA;

    static int smCount = 0;
    if (!smCount) {
        cudaFuncSetAttribute(bond_mlp_s8,
                             cudaFuncAttributeMaxDynamicSharedMemorySize, SMEM_TOTAL);
        cudaDeviceGetAttribute(&smCount, cudaDevAttrMultiProcessorCount, 0);
        if (smCount <= 0) smCount = 148;
    }

    stage_scales<<<1, 256>>>(W1, W2, W3, (const unsigned int*)atom_idx);
    stage_quant<<<89, 256>>>(W1, b1, W2, b2, W3, b3);

    const int grid = (int)((ntiles < smCount) ? ntiles : smCount);
    bond_mlp_s8<<<grid, TPB, SMEM_TOTAL>>>(
        bond_feats, atom_feats, global_feats, atom_idx, global_idx, out, n_bond);
}

// round 15
// speedup vs baseline: 3.3583x; 3.3583x over previous
#include <cuda_runtime.h>
#include <cuda_bf16.h>
#include <cstdint>

#define TPB   256
#define M_CTA 256

// ---------------- smem map (bytes; regions 1024-aligned) ----------------
#define OFF_BIAS 0          // 160 floats
#define OFF_W1H  1024       // 4 segs x [64k][64n] bf16, 8192 B each
#define OFF_W1L  33792
#define OFF_W2H  66560
#define OFF_W2L  74752
#define OFF_W3H  82944      // padded to n=64
#define OFF_W3L  91136
#define STAGE_BYTES 99328   // [0, STAGE_BYTES) is the precomputed image
#define OFF_X0H  99328      // X buffer 0: [256 rows][64 cols] bf16 hi
#define OFF_X0L  132096
#define OFF_X1H  164864     // X buffer 1
#define OFF_X1L  197632
#define SMEM_TOTAL 230400

#define SWZ128(bo) ((bo) ^ (((bo) >> 3) & 0x70))

__device__ __align__(1024) unsigned char g_stage[STAGE_BYTES];
__device__ int g_is64;

// ---------------- PTX wrappers ----------------
__device__ __forceinline__ uint32_t smem_u32(const void* p) {
    uint32_t a;
    asm("{ .reg .u64 t; cvta.to.shared.u64 t, %1; cvt.u32.u64 %0, t; }" : "=r"(a) : "l"(p));
    return a;
}
__device__ __forceinline__ void ldsm4(uint32_t r[4], uint32_t a) {
    asm volatile("ldmatrix.sync.aligned.m8n8.x4.shared.b16 {%0,%1,%2,%3}, [%4];"
        : "=r"(r[0]), "=r"(r[1]), "=r"(r[2]), "=r"(r[3]) : "r"(a));
}
__device__ __forceinline__ void ldsm4t(uint32_t r[4], uint32_t a) {
    asm volatile("ldmatrix.sync.aligned.m8n8.x4.trans.shared.b16 {%0,%1,%2,%3}, [%4];"
        : "=r"(r[0]), "=r"(r[1]), "=r"(r[2]), "=r"(r[3]) : "r"(a));
}
__device__ __forceinline__ void mma16816(float c[4], const uint32_t a[4], const uint32_t b[2]) {
    asm volatile("mma.sync.aligned.m16n8k16.row.col.f32.bf16.bf16.f32 "
        "{%0,%1,%2,%3}, {%4,%5,%6,%7}, {%8,%9}, {%0,%1,%2,%3};"
        : "+f"(c[0]), "+f"(c[1]), "+f"(c[2]), "+f"(c[3])
        : "r"(a[0]), "r"(a[1]), "r"(a[2]), "r"(a[3]), "r"(b[0]), "r"(b[1]));
}

// ---------------- numeric helpers ----------------
__device__ __forceinline__ uint32_t pack_hi2(float a, float b) {
    return (__float_as_uint(a) >> 16) | (__float_as_uint(b) & 0xFFFF0000u);
}
__device__ __forceinline__ uint32_t pack_lo2(float a, float b) {
    float ra = a - __uint_as_float(__float_as_uint(a) & 0xFFFF0000u);
    float rb = b - __uint_as_float(__float_as_uint(b) & 0xFFFF0000u);
    return (__float_as_uint(ra) >> 16) | (__float_as_uint(rb) & 0xFFFF0000u);
}
__device__ __forceinline__ float softplus_f(float v) {
    return fmaxf(v, 0.0f) + __logf(1.0f + __expf(-fabsf(v)));
}

// ---------------------------------------------------------------------------
// precompute split-bf16 swizzled weight image + biases; block 0 also detects
// index dtype (int64 vs int32) from odd 32-bit words of atom_idx.
__global__ void stage_weights(const float* __restrict__ W1, const float* __restrict__ b1,
                              const float* __restrict__ W2, const float* __restrict__ b2,
                              const float* __restrict__ W3, const float* __restrict__ b3,
                              const unsigned int* __restrict__ idxprobe) {
    if (blockIdx.x == 0 && threadIdx.x < 32) {
        unsigned ok = __ballot_sync(0xFFFFFFFFu, idxprobe[2 * threadIdx.x + 1] == 0u);
        if (threadIdx.x == 0) g_is64 = (ok == 0xFFFFFFFFu);
    }
    int t = blockIdx.x * blockDim.x + threadIdx.x;
    unsigned char* st = g_stage;
    if (t < 16384) {                       // W1 [256k][64n]
        int n = t & 63, k = t >> 6;
        float v = W1[t];
        int s = k >> 6, kl = k & 63;
        uint32_t bo = SWZ128((uint32_t)(kl * 128 + n * 2));
        float r = v - __uint_as_float(__float_as_uint(v) & 0xFFFF0000u);
        *(unsigned short*)(st + OFF_W1H + s * 8192 + bo) = (unsigned short)(__float_as_uint(v) >> 16);
        *(unsigned short*)(st + OFF_W1L + s * 8192 + bo) = (unsigned short)(__float_as_uint(r) >> 16);
    } else if (t < 20480) {                // W2 [64][64]
        int i = t - 16384;
        int n = i & 63, k = i >> 6;
        float v = W2[i];
        uint32_t bo = SWZ128((uint32_t)(k * 128 + n * 2));
        float r = v - __uint_as_float(__float_as_uint(v) & 0xFFFF0000u);
        *(unsigned short*)(st + OFF_W2H + bo) = (unsigned short)(__float_as_uint(v) >> 16);
        *(unsigned short*)(st + OFF_W2L + bo) = (unsigned short)(__float_as_uint(r) >> 16);
    } else if (t < 24576) {                // W3 [64][32] padded to n=64
        int i = t - 20480;
        int n = i & 63, k = i >> 6;
        float v = (n < 32) ? W3[k * 32 + n] : 0.0f;
        uint32_t bo = SWZ128((uint32_t)(k * 128 + n * 2));
        float r = v - __uint_as_float(__float_as_uint(v) & 0xFFFF0000u);
        *(unsigned short*)(st + OFF_W3H + bo) = (unsigned short)(__float_as_uint(v) >> 16);
        *(unsigned short*)(st + OFF_W3L + bo) = (unsigned short)(__float_as_uint(r) >> 16);
    } else if (t < 24576 + 64) {
        ((float*)(st + OFF_BIAS))[t - 24576] = b1[t - 24576];
    } else if (t < 24576 + 128) {
        ((float*)(st + OFF_BIAS))[t - 24576] = b2[t - 24640];
    } else if (t < 24576 + 160) {
        ((float*)(st + OFF_BIAS))[t - 24576] = b3[t - 24704];
    }
}

// ---------------- cooperative gather ----------------
struct GatherCtx {
    const float* bond; const float* atom; const float* glob;
    const void* aidx; const void* gidx;
    int n_bond; int is64; int lb; int part;
};

template<int SEG>
__device__ __forceinline__ void load_chunk(const GatherCtx& c, long long base,
                                           int r0, float4 v[8]) {
    #pragma unroll
    for (int i = 0; i < 8; i++) {
        const int bl = (r0 + i) * 16 + c.lb;
        const long long gb = base + bl;
        const size_t bond = (size_t)((gb < c.n_bond) ? gb : (c.n_bond - 1));
        size_t row; const float* bp;
        if (SEG == 0) { row = bond; bp = c.bond; }
        else if (SEG == 3) {
            row = c.is64 ? (size_t)((const long long*)c.gidx)[bond]
                         : (size_t)((const int*)c.gidx)[bond];
            bp = c.glob;
        } else {
            row = c.is64 ? (size_t)((const long long*)c.aidx)[2 * bond + (SEG - 1)]
                         : (size_t)((const int*)c.aidx)[2 * bond + (SEG - 1)];
            bp = c.atom;
        }
        v[i] = ((const float4*)(bp + row * 64))[c.part];
    }
}

__device__ __forceinline__ void sts_chunk(char* smem, uint32_t offH, uint32_t offL,
                                          int lb, int part, int r0, const float4 v[8]) {
    #pragma unroll
    for (int i = 0; i < 8; i++) {
        const int bl = (r0 + i) * 16 + lb;
        const uint32_t bo = SWZ128((uint32_t)(bl * 128 + part * 8));
        uint64_t hi = ((uint64_t)pack_hi2(v[i].z, v[i].w) << 32) | pack_hi2(v[i].x, v[i].y);
        uint64_t lo = ((uint64_t)pack_lo2(v[i].z, v[i].w) << 32) | pack_lo2(v[i].x, v[i].y);
        *(uint64_t*)(smem + offH + bo) = hi;
        *(uint64_t*)(smem + offL + bo) = lo;
    }
}

// ---- 3-pass MMA issue over an nb-pair: same-acc reuse distance = 8 issues ---
// accs: 8 distinct quads (2 nb x 2 h x 2 mt) per pass.
#define MMA_PAIR_PASSES(acc, NT, nb0)                                          \
    do {                                                                       \
        /* pass 1: Ah*Bh */                                                    \
        _Pragma("unroll") for (int j = 0; j < 2; j++)                          \
        _Pragma("unroll") for (int h2 = 0; h2 < 2; h2++) {                     \
            const uint32_t bf[2] = { bh[j][2*h2], bh[j][2*h2+1] };             \
            const int nt = (nb0 + j) * 2 + h2;                                 \
            mma16816(acc[0 * (NT) + nt], ah0, bf);                             \
            mma16816(acc[1 * (NT) + nt], ah1, bf);                             \
        }                                                                      \
        /* pass 2: Ah*Bl */                                                    \
        _Pragma("unroll") for (int j = 0; j < 2; j++)                          \
        _Pragma("unroll") for (int h2 = 0; h2 < 2; h2++) {                     \
            const uint32_t bf[2] = { bl[j][2*h2], bl[j][2*h2+1] };             \
            const int nt = (nb0 + j) * 2 + h2;                                 \
            mma16816(acc[0 * (NT) + nt], ah0, bf);                             \
            mma16816(acc[1 * (NT) + nt], ah1, bf);                             \
        }                                                                      \
        /* pass 3: Al*Bh */                                                    \
        _Pragma("unroll") for (int j = 0; j < 2; j++)                          \
        _Pragma("unroll") for (int h2 = 0; h2 < 2; h2++) {                     \
            const uint32_t bf[2] = { bh[j][2*h2], bh[j][2*h2+1] };             \
            const int nt = (nb0 + j) * 2 + h2;                                 \
            mma16816(acc[0 * (NT) + nt], al0, bf);                             \
            mma16816(acc[1 * (NT) + nt], al1, bf);                             \
        }                                                                      \
    } while (0)

// ---------------- warp-level GEMM (M=32), A from smem: kt in [KT0, KT1) ------
template<int NT, int KT0, int KT1>
__device__ __forceinline__ void gemm_part(uint32_t sb,
                                          uint32_t offAH, uint32_t offAL,
                                          uint32_t offBH, uint32_t offBL,
                                          int m0, int lane, float acc[][4]) {
    #pragma unroll
    for (int kt = KT0; kt < KT1; kt++) {
        const int k0 = kt * 16;
        uint32_t ah0[4], ah1[4], al0[4], al1[4];
        {
            int row = m0 + (lane & 15);
            uint32_t bo0 = SWZ128((uint32_t)(row * 128 + k0 * 2 + ((lane >> 4) << 4)));
            uint32_t bo1 = SWZ128((uint32_t)((row + 16) * 128 + k0 * 2 + ((lane >> 4) << 4)));
            ldsm4(ah0, sb + offAH + bo0);
            ldsm4(ah1, sb + offAH + bo1);
            ldsm4(al0, sb + offAL + bo0);
            ldsm4(al1, sb + offAL + bo1);
        }
        #pragma unroll
        for (int nbp = 0; nbp < NT / 4; nbp++) {
            uint32_t bh[2][4], bl[2][4];
            const int krow = k0 + (lane & 15);
            #pragma unroll
            for (int j = 0; j < 2; j++) {
                uint32_t bo = SWZ128((uint32_t)(krow * 128 + (nbp * 2 + j) * 32 + ((lane >> 4) << 4)));
                ldsm4t(bh[j], sb + offBH + bo);
                ldsm4t(bl[j], sb + offBL + bo);
            }
            MMA_PAIR_PASSES(acc, NT, nbp * 2);
        }
    }
}

// ---------------- warp-level GEMM (M=32), A from pre-packed fragments --------
template<int NT, int KT0, int KT1>
__device__ __forceinline__ void gemm_regA(uint32_t sb,
                                          const uint32_t aph[2][4][4],
                                          const uint32_t alp[2][4][4],
                                          uint32_t offBH, uint32_t offBL,
                                          int lane, float acc[][4]) {
    #pragma unroll
    for (int kt = KT0; kt < KT1; kt++) {
        const int k0 = kt * 16;
        const uint32_t* ah0 = aph[0][kt];
        const uint32_t* ah1 = aph[1][kt];
        const uint32_t* al0 = alp[0][kt];
        const uint32_t* al1 = alp[1][kt];
        #pragma unroll
        for (int nbp = 0; nbp < NT / 4; nbp++) {
            uint32_t bh[2][4], bl[2][4];
            const int krow = k0 + (lane & 15);
            #pragma unroll
            for (int j = 0; j < 2; j++) {
                uint32_t bo = SWZ128((uint32_t)(krow * 128 + (nbp * 2 + j) * 32 + ((lane >> 4) << 4)));
                ldsm4t(bh[j], sb + offBH + bo);
                ldsm4t(bl[j], sb + offBL + bo);
            }
            MMA_PAIR_PASSES(acc, NT, nbp * 2);
        }
    }
}

// bias + softplus in place on 16 C-fragments (M=32 warp tile)
__device__ __forceinline__ void act_inplace(float acc[][4], const float* bias, int lane) {
    #pragma unroll
    for (int i = 0; i < 16; i++) {
        const int col = (i & 7) * 8 + (lane & 3) * 2;
        const float b0 = bias[col], b1 = bias[col + 1];
        acc[i][0] = softplus_f(acc[i][0] + b0);
        acc[i][1] = softplus_f(acc[i][1] + b1);
        acc[i][2] = softplus_f(acc[i][2] + b0);
        acc[i][3] = softplus_f(acc[i][3] + b1);
    }
}

// pack activated C-fragments into split-bf16 A-fragments (once per layer)
__device__ __forceinline__ void pack_h(const float acc[][4],
                                       uint32_t aph[2][4][4], uint32_t alp[2][4][4]) {
    #pragma unroll
    for (int mt = 0; mt < 2; mt++)
    #pragma unroll
    for (int kt = 0; kt < 4; kt++) {
        const float* t0 = acc[mt * 8 + 2 * kt];
        const float* t1 = acc[mt * 8 + 2 * kt + 1];
        aph[mt][kt][0] = pack_hi2(t0[0], t0[1]);
        aph[mt][kt][1] = pack_hi2(t0[2], t0[3]);
        aph[mt][kt][2] = pack_hi2(t1[0], t1[1]);
        aph[mt][kt][3] = pack_hi2(t1[2], t1[3]);
        alp[mt][kt][0] = pack_lo2(t0[0], t0[1]);
        alp[mt][kt][1] = pack_lo2(t0[2], t0[3]);
        alp[mt][kt][2] = pack_lo2(t1[0], t1[1]);
        alp[mt][kt][3] = pack_lo2(t1[2], t1[3]);
    }
}

// ---------------------------------------------------------------------------
__global__ __launch_bounds__(TPB, 1)
void bond_mlp_mma(const float* __restrict__ bond_feats,
                  const float* __restrict__ atom_feats,
                  const float* __restrict__ global_feats,
                  const void*  __restrict__ atom_idx,
                  const void*  __restrict__ global_idx,
                  float* __restrict__ out, int n_bond)
{
    extern __shared__ char smem[];
    const uint32_t sb = smem_u32(smem);
    const int tid  = threadIdx.x;
    const int wid  = tid >> 5;
    const int lane = tid & 31;
    const int m0   = wid * 32;

    GatherCtx ctx;
    ctx.bond = bond_feats; ctx.atom = atom_feats; ctx.glob = global_feats;
    ctx.aidx = atom_idx;   ctx.gidx = global_idx;
    ctx.n_bond = n_bond;   ctx.is64 = g_is64;
    ctx.lb = tid >> 4;     ctx.part = tid & 15;

    const long long ntiles = (n_bond + M_CTA - 1) / M_CTA;
    long long tile = blockIdx.x;
    long long base = tile * M_CTA;

    float4 v[8];

    // prologue: seg0 of first tile LDGs in flight during the one-time weight copy
    load_chunk<0>(ctx, base, 0, v);
    {
        const float4* src = (const float4*)g_stage;
        float4* dst = (float4*)smem;
        #pragma unroll 5
        for (int i = tid; i < STAGE_BYTES / 16; i += TPB) dst[i] = src[i];
    }
    sts_chunk(smem, OFF_X0H, OFF_X0L, ctx.lb, ctx.part, 0, v);
    load_chunk<0>(ctx, base, 8, v);
    sts_chunk(smem, OFF_X0H, OFF_X0L, ctx.lb, ctx.part, 8, v);
    __syncthreads();

    // persistent tile loop; invariant on entry: X0 holds seg0 of `tile`, synced
    #pragma unroll 1
    while (true) {
        float acc[16][4];
        #pragma unroll
        for (int i = 0; i < 16; i++)
            #pragma unroll
            for (int q = 0; q < 4; q++) acc[i][q] = 0.0f;

        // ---- L1 seg0 (reads X0, prefetch seg1 -> X1) ----
        load_chunk<1>(ctx, base, 0, v);
        gemm_part<8, 0, 2>(sb, OFF_X0H, OFF_X0L, OFF_W1H, OFF_W1L, m0, lane, acc);
        sts_chunk(smem, OFF_X1H, OFF_X1L, ctx.lb, ctx.part, 0, v);
        load_chunk<1>(ctx, base, 8, v);
        gemm_part<8, 2, 4>(sb, OFF_X0H, OFF_X0L, OFF_W1H, OFF_W1L, m0, lane, acc);
        sts_chunk(smem, OFF_X1H, OFF_X1L, ctx.lb, ctx.part, 8, v);
        __syncthreads();

        // ---- seg1 (reads X1, prefetch seg2 -> X0) ----
        load_chunk<2>(ctx, base, 0, v);
        gemm_part<8, 0, 2>(sb, OFF_X1H, OFF_X1L, OFF_W1H + 8192, OFF_W1L + 8192, m0, lane, acc);
        sts_chunk(smem, OFF_X0H, OFF_X0L, ctx.lb, ctx.part, 0, v);
        load_chunk<2>(ctx, base, 8, v);
        gemm_part<8, 2, 4>(sb, OFF_X1H, OFF_X1L, OFF_W1H + 8192, OFF_W1L + 8192, m0, lane, acc);
        sts_chunk(smem, OFF_X0H, OFF_X0L, ctx.lb, ctx.part, 8, v);
        __syncthreads();

        // ---- seg2 (reads X0, prefetch seg3 -> X1) ----
        load_chunk<3>(ctx, base, 0, v);
        gemm_part<8, 0, 2>(sb, OFF_X0H, OFF_X0L, OFF_W1H + 16384, OFF_W1L + 16384, m0, lane, acc);
        sts_chunk(smem, OFF_X1H, OFF_X1L, ctx.lb, ctx.part, 0, v);
        load_chunk<3>(ctx, base, 8, v);
        gemm_part<8, 2, 4>(sb, OFF_X0H, OFF_X0L, OFF_W1H + 16384, OFF_W1L + 16384, m0, lane, acc);
        sts_chunk(smem, OFF_X1H, OFF_X1L, ctx.lb, ctx.part, 8, v);
        __syncthreads();

        // ---- seg3 (reads X1) ----
        gemm_part<8, 0, 4>(sb, OFF_X1H, OFF_X1L, OFF_W1H + 24576, OFF_W1L + 24576, m0, lane, acc);

        // ---- h1 = softplus(acc + b1); pack ONCE to split-bf16 fragments ----
        act_inplace(acc, (const float*)(smem + OFF_BIAS), lane);
        uint32_t aph[2][4][4], alp[2][4][4];
        pack_h(acc, aph, alp);          // acc dead after this

        // ---- L2 (A from packed registers); prefetch next tile seg0 -> X0 ---
        const long long ntile = tile + gridDim.x;
        const bool more = (ntile < ntiles);
        const long long nbase = ntile * M_CTA;

        float acc2[16][4];
        #pragma unroll
        for (int i = 0; i < 16; i++)
            #pragma unroll
            for (int q = 0; q < 4; q++) acc2[i][q] = 0.0f;

        if (more) load_chunk<0>(ctx, nbase, 0, v);
        gemm_regA<8, 0, 2>(sb, aph, alp, OFF_W2H, OFF_W2L, lane, acc2);
        if (more) { sts_chunk(smem, OFF_X0H, OFF_X0L, ctx.lb, ctx.part, 0, v);
                    load_chunk<0>(ctx, nbase, 8, v); }
        gemm_regA<8, 2, 4>(sb, aph, alp, OFF_W2H, OFF_W2L, lane, acc2);
        if (more) sts_chunk(smem, OFF_X0H, OFF_X0L, ctx.lb, ctx.part, 8, v);

        // ---- h2 = softplus(acc2 + b2); pack (reuse fragment regs) ----
        act_inplace(acc2, (const float*)(smem + OFF_BIAS) + 64, lane);
        pack_h(acc2, aph, alp);         // acc2 dead after this

        // ---- L3 (A from packed registers, N=32) ----
        float acc3[8][4];
        #pragma unroll
        for (int i = 0; i < 8; i++)
            #pragma unroll
            for (int q = 0; q < 4; q++) acc3[i][q] = 0.0f;
        gemm_regA<4, 0, 4>(sb, aph, alp, OFF_W3H, OFF_W3L, lane, acc3);

        // ---- output: acc3 + b3 -> global ----
        {
            const float* bias = (const float*)(smem + OFF_BIAS) + 128;
            #pragma unroll
            for (int mt = 0; mt < 2; mt++)
            #pragma unroll
            for (int nt = 0; nt < 4; nt++) {
                const int col = nt * 8 + (lane & 3) * 2;
                const float bv0 = bias[col], bv1 = bias[col + 1];
                #pragma unroll
                for (int h = 0; h < 2; h++) {
                    const int row = m0 + mt * 16 + (lane >> 2) + h * 8;
                    const long long gb = base + row;
                    if (gb < n_bond) {
                        float2 o = make_float2(acc3[mt * 4 + nt][2 * h]     + bv0,
                                               acc3[mt * 4 + nt][2 * h + 1] + bv1);
                        *(float2*)(out + (size_t)gb * 32 + col) = o;
                    }
                }
            }
        }

        if (!more) break;
        tile = ntile; base = nbase;
        __syncthreads();   // X0 (next seg0) visible; X1 seg3 reads complete
    }
}

// ---------------------------------------------------------------------------
extern "C" void kernel_launch(void* const* d_in, const int* in_sizes, int n_in,
                              void* d_out, int out_size)
{
    const float* bond_feats   = (const float*)d_in[0];
    const float* atom_feats   = (const float*)d_in[1];
    const float* global_feats = (const float*)d_in[2];
    const void*  atom_idx     = d_in[3];
    const void*  global_idx   = d_in[4];
    const float* W1 = (const float*)d_in[5];
    const float* b1 = (const float*)d_in[6];
    const float* W2 = (const float*)d_in[7];
    const float* b2 = (const float*)d_in[8];
    const float* W3 = (const float*)d_in[9];
    const float* b3 = (const float*)d_in[10];
    float* out = (float*)d_out;

    const int n_bond = in_sizes[0] / 64;
    const long long ntiles = (n_bond + M_CTA - 1) / M_CTA;

    static int smCount = 0;
    if (!smCount) {
        cudaFuncSetAttribute(bond_mlp_mma,
                             cudaFuncAttributeMaxDynamicSharedMemorySize, SMEM_TOTAL);
        cudaDeviceGetAttribute(&smCount, cudaDevAttrMultiProcessorCount, 0);
        if (smCount <= 0) smCount = 148;
    }

    stage_weights<<<97, 256>>>(W1, b1, W2, b2, W3, b3, (const unsigned int*)atom_idx);

    const int grid = (int)((ntiles < smCount) ? ntiles : smCount);
    bond_mlp_mma<<<grid, TPB, SMEM_TOTAL>>>(
        bond_feats, atom_feats, global_feats, atom_idx, global_idx, out, n_bond);
}

// round 17
// speedup vs baseline: 4.0764x; 1.2138x over previous
#include <cuda_runtime.h>
#include <cuda_fp16.h>
#include <cstdint>

#define TPB   256
#define M_CTA 256

// ---------------- smem map (bytes; regions 1024-aligned) ----------------
#define OFF_BIAS 0          // 160 floats
#define OFF_W1   1024       // 4 segs x [64k][64n] fp16, 8192 B each
#define OFF_W2   33792      // [64k][64n] fp16
#define OFF_W3   41984      // [64k][64n] fp16 (n 32..63 zero)
#define STAGE_BYTES 50176   // [0, STAGE_BYTES) is the precomputed image
#define OFF_X0H  50176      // X buffer 0: [256 rows][64 cols] fp16 hi
#define OFF_X0L  82944
#define OFF_X1H  115712     // X buffer 1
#define OFF_X1L  148480
#define SMEM_TOTAL 181248

#define SWZ128(bo) ((bo) ^ (((bo) >> 3) & 0x70))

__device__ __align__(1024) unsigned char g_stage[STAGE_BYTES];
__device__ int g_is64;

// ---------------- PTX wrappers ----------------
__device__ __forceinline__ uint32_t smem_u32(const void* p) {
    uint32_t a;
    asm("{ .reg .u64 t; cvta.to.shared.u64 t, %1; cvt.u32.u64 %0, t; }" : "=r"(a) : "l"(p));
    return a;
}
__device__ __forceinline__ void ldsm4(uint32_t r[4], uint32_t a) {
    asm volatile("ldmatrix.sync.aligned.m8n8.x4.shared.b16 {%0,%1,%2,%3}, [%4];"
        : "=r"(r[0]), "=r"(r[1]), "=r"(r[2]), "=r"(r[3]) : "r"(a));
}
__device__ __forceinline__ void ldsm4t(uint32_t r[4], uint32_t a) {
    asm volatile("ldmatrix.sync.aligned.m8n8.x4.trans.shared.b16 {%0,%1,%2,%3}, [%4];"
        : "=r"(r[0]), "=r"(r[1]), "=r"(r[2]), "=r"(r[3]) : "r"(a));
}
__device__ __forceinline__ void mma16816(float c[4], const uint32_t a[4], const uint32_t b[2]) {
    asm volatile("mma.sync.aligned.m16n8k16.row.col.f32.f16.f16.f32 "
        "{%0,%1,%2,%3}, {%4,%5,%6,%7}, {%8,%9}, {%0,%1,%2,%3};"
        : "+f"(c[0]), "+f"(c[1]), "+f"(c[2]), "+f"(c[3])
        : "r"(a[0]), "r"(a[1]), "r"(a[2]), "r"(a[3]), "r"(b[0]), "r"(b[1]));
}

// ---------------- numeric helpers ----------------
__device__ __forceinline__ uint32_t pack_h16(float a, float b) {
    __half2 h = __floats2half2_rn(a, b);
    return *reinterpret_cast<uint32_t*>(&h);
}
__device__ __forceinline__ uint32_t pack_l16(float a, float b) {
    float ra = a - __half2float(__float2half_rn(a));
    float rb = b - __half2float(__float2half_rn(b));
    __half2 h = __floats2half2_rn(ra, rb);
    return *reinterpret_cast<uint32_t*>(&h);
}
__device__ __forceinline__ float softplus_f(float v) {
    return fmaxf(v, 0.0f) + __logf(1.0f + __expf(-fabsf(v)));
}

// ---------------------------------------------------------------------------
// precompute fp16 swizzled weight image + biases; block 0 also detects
// index dtype (int64 vs int32) from odd 32-bit words of atom_idx.
__global__ void stage_weights(const float* __restrict__ W1, const float* __restrict__ b1,
                              const float* __restrict__ W2, const float* __restrict__ b2,
                              const float* __restrict__ W3, const float* __restrict__ b3,
                              const unsigned int* __restrict__ idxprobe) {
    if (blockIdx.x == 0 && threadIdx.x < 32) {
        unsigned ok = __ballot_sync(0xFFFFFFFFu, idxprobe[2 * threadIdx.x + 1] == 0u);
        if (threadIdx.x == 0) g_is64 = (ok == 0xFFFFFFFFu);
    }
    int t = blockIdx.x * blockDim.x + threadIdx.x;
    unsigned char* st = g_stage;
    if (t < 16384) {                       // W1 [256k][64n]
        int n = t & 63, k = t >> 6;
        int s = k >> 6, kl = k & 63;
        __half hv = __float2half_rn(W1[t]);
        uint32_t bo = SWZ128((uint32_t)(kl * 128 + n * 2));
        *(unsigned short*)(st + OFF_W1 + s * 8192 + bo) = *reinterpret_cast<unsigned short*>(&hv);
    } else if (t < 20480) {                // W2 [64][64]
        int i = t - 16384;
        int n = i & 63, k = i >> 6;
        __half hv = __float2half_rn(W2[i]);
        uint32_t bo = SWZ128((uint32_t)(k * 128 + n * 2));
        *(unsigned short*)(st + OFF_W2 + bo) = *reinterpret_cast<unsigned short*>(&hv);
    } else if (t < 24576) {                // W3 [64][32] padded to n=64
        int i = t - 20480;
        int n = i & 63, k = i >> 6;
        float v = (n < 32) ? W3[k * 32 + n] : 0.0f;
        __half hv = __float2half_rn(v);
        uint32_t bo = SWZ128((uint32_t)(k * 128 + n * 2));
        *(unsigned short*)(st + OFF_W3 + bo) = *reinterpret_cast<unsigned short*>(&hv);
    } else if (t < 24576 + 64) {
        ((float*)(st + OFF_BIAS))[t - 24576] = b1[t - 24576];
    } else if (t < 24576 + 128) {
        ((float*)(st + OFF_BIAS))[t - 24576] = b2[t - 24640];
    } else if (t < 24576 + 160) {
        ((float*)(st + OFF_BIAS))[t - 24576] = b3[t - 24704];
    }
}

// ---------------- cooperative gather ----------------
struct GatherCtx {
    const float* bond; const float* atom; const float* glob;
    const void* aidx; const void* gidx;
    int n_bond; int is64; int lb; int part;
};

template<int SEG>
__device__ __forceinline__ void load_chunk(const GatherCtx& c, long long base,
                                           int r0, float4 v[8]) {
    #pragma unroll
    for (int i = 0; i < 8; i++) {
        const int bl = (r0 + i) * 16 + c.lb;
        const long long gb = base + bl;
        const size_t bond = (size_t)((gb < c.n_bond) ? gb : (c.n_bond - 1));
        size_t row; const float* bp;
        if (SEG == 0) { row = bond; bp = c.bond; }
        else if (SEG == 3) {
            row = c.is64 ? (size_t)((const long long*)c.gidx)[bond]
                         : (size_t)((const int*)c.gidx)[bond];
            bp = c.glob;
        } else {
            row = c.is64 ? (size_t)((const long long*)c.aidx)[2 * bond + (SEG - 1)]
                         : (size_t)((const int*)c.aidx)[2 * bond + (SEG - 1)];
            bp = c.atom;
        }
        v[i] = ((const float4*)(bp + row * 64))[c.part];
    }
}

__device__ __forceinline__ void sts_chunk(char* smem, uint32_t offH, uint32_t offL,
                                          int lb, int part, int r0, const float4 v[8]) {
    #pragma unroll
    for (int i = 0; i < 8; i++) {
        const int bl = (r0 + i) * 16 + lb;
        const uint32_t bo = SWZ128((uint32_t)(bl * 128 + part * 8));
        uint64_t hi = ((uint64_t)pack_h16(v[i].z, v[i].w) << 32) | pack_h16(v[i].x, v[i].y);
        uint64_t lo = ((uint64_t)pack_l16(v[i].z, v[i].w) << 32) | pack_l16(v[i].x, v[i].y);
        *(uint64_t*)(smem + offH + bo) = hi;
        *(uint64_t*)(smem + offL + bo) = lo;
    }
}

// ---- 2-pass MMA issue over an nb-pair: same-acc reuse distance = 8 issues ---
#define MMA_PAIR_PASSES(acc, NT, nb0)                                          \
    do {                                                                       \
        /* pass 1: Ah*B */                                                     \
        _Pragma("unroll") for (int j = 0; j < 2; j++)                          \
        _Pragma("unroll") for (int h2 = 0; h2 < 2; h2++) {                     \
            const uint32_t bf[2] = { bh[j][2*h2], bh[j][2*h2+1] };             \
            const int nt = (nb0 + j) * 2 + h2;                                 \
            mma16816(acc[0 * (NT) + nt], ah0, bf);                             \
            mma16816(acc[1 * (NT) + nt], ah1, bf);                             \
        }                                                                      \
        /* pass 2: Al*B */                                                     \
        _Pragma("unroll") for (int j = 0; j < 2; j++)                          \
        _Pragma("unroll") for (int h2 = 0; h2 < 2; h2++) {                     \
            const uint32_t bf[2] = { bh[j][2*h2], bh[j][2*h2+1] };             \
            const int nt = (nb0 + j) * 2 + h2;                                 \
            mma16816(acc[0 * (NT) + nt], al0, bf);                             \
            mma16816(acc[1 * (NT) + nt], al1, bf);                             \
        }                                                                      \
    } while (0)

// ---------------- warp-level GEMM (M=32), A from smem: kt in [KT0, KT1) ------
template<int NT, int KT0, int KT1>
__device__ __forceinline__ void gemm_part(uint32_t sb,
                                          uint32_t offAH, uint32_t offAL,
                                          uint32_t offB,
                                          int m0, int lane, float acc[][4]) {
    #pragma unroll
    for (int kt = KT0; kt < KT1; kt++) {
        const int k0 = kt * 16;
        uint32_t ah0[4], ah1[4], al0[4], al1[4];
        {
            int row = m0 + (lane & 15);
            uint32_t bo0 = SWZ128((uint32_t)(row * 128 + k0 * 2 + ((lane >> 4) << 4)));
            uint32_t bo1 = SWZ128((uint32_t)((row + 16) * 128 + k0 * 2 + ((lane >> 4) << 4)));
            ldsm4(ah0, sb + offAH + bo0);
            ldsm4(ah1, sb + offAH + bo1);
            ldsm4(al0, sb + offAL + bo0);
            ldsm4(al1, sb + offAL + bo1);
        }
        #pragma unroll
        for (int nbp = 0; nbp < NT / 4; nbp++) {
            uint32_t bh[2][4];
            const int krow = k0 + (lane & 15);
            #pragma unroll
            for (int j = 0; j < 2; j++) {
                uint32_t bo = SWZ128((uint32_t)(krow * 128 + (nbp * 2 + j) * 32 + ((lane >> 4) << 4)));
                ldsm4t(bh[j], sb + offB + bo);
            }
            MMA_PAIR_PASSES(acc, NT, nbp * 2);
        }
    }
}

// ---------------- warp-level GEMM (M=32), A from pre-packed fragments --------
template<int NT, int KT0, int KT1>
__device__ __forceinline__ void gemm_regA(uint32_t sb,
                                          const uint32_t aph[2][4][4],
                                          const uint32_t alp[2][4][4],
                                          uint32_t offB,
                                          int lane, float acc[][4]) {
    #pragma unroll
    for (int kt = KT0; kt < KT1; kt++) {
        const int k0 = kt * 16;
        const uint32_t* ah0 = aph[0][kt];
        const uint32_t* ah1 = aph[1][kt];
        const uint32_t* al0 = alp[0][kt];
        const uint32_t* al1 = alp[1][kt];
        #pragma unroll
        for (int nbp = 0; nbp < NT / 4; nbp++) {
            uint32_t bh[2][4];
            const int krow = k0 + (lane & 15);
            #pragma unroll
            for (int j = 0; j < 2; j++) {
                uint32_t bo = SWZ128((uint32_t)(krow * 128 + (nbp * 2 + j) * 32 + ((lane >> 4) << 4)));
                ldsm4t(bh[j], sb + offB + bo);
            }
            MMA_PAIR_PASSES(acc, NT, nbp * 2);
        }
    }
}

// bias + softplus in place on 16 C-fragments (M=32 warp tile)
__device__ __forceinline__ void act_inplace(float acc[][4], const float* bias, int lane) {
    #pragma unroll
    for (int i = 0; i < 16; i++) {
        const int col = (i & 7) * 8 + (lane & 3) * 2;
        const float b0 = bias[col], b1 = bias[col + 1];
        acc[i][0] = softplus_f(acc[i][0] + b0);
        acc[i][1] = softplus_f(acc[i][1] + b1);
        acc[i][2] = softplus_f(acc[i][2] + b0);
        acc[i][3] = softplus_f(acc[i][3] + b1);
    }
}

// pack activated C-fragments into exact fp16 hi/lo A-fragments (once per layer)
__device__ __forceinline__ void pack_h(const float acc[][4],
                                       uint32_t aph[2][4][4], uint32_t alp[2][4][4]) {
    #pragma unroll
    for (int mt = 0; mt < 2; mt++)
    #pragma unroll
    for (int kt = 0; kt < 4; kt++) {
        const float* t0 = acc[mt * 8 + 2 * kt];
        const float* t1 = acc[mt * 8 + 2 * kt + 1];
        aph[mt][kt][0] = pack_h16(t0[0], t0[1]);
        aph[mt][kt][1] = pack_h16(t0[2], t0[3]);
        aph[mt][kt][2] = pack_h16(t1[0], t1[1]);
        aph[mt][kt][3] = pack_h16(t1[2], t1[3]);
        alp[mt][kt][0] = pack_l16(t0[0], t0[1]);
        alp[mt][kt][1] = pack_l16(t0[2], t0[3]);
        alp[mt][kt][2] = pack_l16(t1[0], t1[1]);
        alp[mt][kt][3] = pack_l16(t1[2], t1[3]);
    }
}

// ---------------------------------------------------------------------------
__global__ __launch_bounds__(TPB, 1)
void bond_mlp_mma(const float* __restrict__ bond_feats,
                  const float* __restrict__ atom_feats,
                  const float* __restrict__ global_feats,
                  const void*  __restrict__ atom_idx,
                  const void*  __restrict__ global_idx,
                  float* __restrict__ out, int n_bond)
{
    extern __shared__ char smem[];
    const uint32_t sb = smem_u32(smem);
    const int tid  = threadIdx.x;
    const int wid  = tid >> 5;
    const int lane = tid & 31;
    const int m0   = wid * 32;

    GatherCtx ctx;
    ctx.bond = bond_feats; ctx.atom = atom_feats; ctx.glob = global_feats;
    ctx.aidx = atom_idx;   ctx.gidx = global_idx;
    ctx.n_bond = n_bond;   ctx.is64 = g_is64;
    ctx.lb = tid >> 4;     ctx.part = tid & 15;

    const long long ntiles = (n_bond + M_CTA - 1) / M_CTA;
    long long tile = blockIdx.x;
    long long base = tile * M_CTA;

    float4 v[8];

    // prologue: seg0 of first tile LDGs in flight during the one-time weight copy
    load_chunk<0>(ctx, base, 0, v);
    {
        const float4* src = (const float4*)g_stage;
        float4* dst = (float4*)smem;
        #pragma unroll 5
        for (int i = tid; i < STAGE_BYTES / 16; i += TPB) dst[i] = src[i];
    }
    sts_chunk(smem, OFF_X0H, OFF_X0L, ctx.lb, ctx.part, 0, v);
    load_chunk<0>(ctx, base, 8, v);
    sts_chunk(smem, OFF_X0H, OFF_X0L, ctx.lb, ctx.part, 8, v);
    __syncthreads();

    // persistent tile loop; invariant on entry: X0 holds seg0 of `tile`, synced
    #pragma unroll 1
    while (true) {
        float acc[16][4];
        #pragma unroll
        for (int i = 0; i < 16; i++)
            #pragma unroll
            for (int q = 0; q < 4; q++) acc[i][q] = 0.0f;

        // ---- L1 seg0 (reads X0, prefetch seg1 -> X1) ----
        load_chunk<1>(ctx, base, 0, v);
        gemm_part<8, 0, 2>(sb, OFF_X0H, OFF_X0L, OFF_W1, m0, lane, acc);
        sts_chunk(smem, OFF_X1H, OFF_X1L, ctx.lb, ctx.part, 0, v);
        load_chunk<1>(ctx, base, 8, v);
        gemm_part<8, 2, 4>(sb, OFF_X0H, OFF_X0L, OFF_W1, m0, lane, acc);
        sts_chunk(smem, OFF_X1H, OFF_X1L, ctx.lb, ctx.part, 8, v);
        __syncthreads();

        // ---- seg1 (reads X1, prefetch seg2 -> X0) ----
        load_chunk<2>(ctx, base, 0, v);
        gemm_part<8, 0, 2>(sb, OFF_X1H, OFF_X1L, OFF_W1 + 8192, m0, lane, acc);
        sts_chunk(smem, OFF_X0H, OFF_X0L, ctx.lb, ctx.part, 0, v);
        load_chunk<2>(ctx, base, 8, v);
        gemm_part<8, 2, 4>(sb, OFF_X1H, OFF_X1L, OFF_W1 + 8192, m0, lane, acc);
        sts_chunk(smem, OFF_X0H, OFF_X0L, ctx.lb, ctx.part, 8, v);
        __syncthreads();

        // ---- seg2 (reads X0, prefetch seg3 -> X1) ----
        load_chunk<3>(ctx, base, 0, v);
        gemm_part<8, 0, 2>(sb, OFF_X0H, OFF_X0L, OFF_W1 + 16384, m0, lane, acc);
        sts_chunk(smem, OFF_X1H, OFF_X1L, ctx.lb, ctx.part, 0, v);
        load_chunk<3>(ctx, base, 8, v);
        gemm_part<8, 2, 4>(sb, OFF_X0H, OFF_X0L, OFF_W1 + 16384, m0, lane, acc);
        sts_chunk(smem, OFF_X1H, OFF_X1L, ctx.lb, ctx.part, 8, v);
        __syncthreads();

        // ---- seg3 (reads X1) ----
        gemm_part<8, 0, 4>(sb, OFF_X1H, OFF_X1L, OFF_W1 + 24576, m0, lane, acc);

        // ---- h1 = softplus(acc + b1); pack ONCE to fp16 hi/lo fragments ----
        act_inplace(acc, (const float*)(smem + OFF_BIAS), lane);
        uint32_t aph[2][4][4], alp[2][4][4];
        pack_h(acc, aph, alp);          // acc dead after this

        // ---- L2 (A from packed registers); prefetch next tile seg0 -> X0 ---
        const long long ntile = tile + gridDim.x;
        const bool more = (ntile < ntiles);
        const long long nbase = ntile * M_CTA;

        float acc2[16][4];
        #pragma unroll
        for (int i = 0; i < 16; i++)
            #pragma unroll
            for (int q = 0; q < 4; q++) acc2[i][q] = 0.0f;

        if (more) load_chunk<0>(ctx, nbase, 0, v);
        gemm_regA<8, 0, 2>(sb, aph, alp, OFF_W2, lane, acc2);
        if (more) { sts_chunk(smem, OFF_X0H, OFF_X0L, ctx.lb, ctx.part, 0, v);
                    load_chunk<0>(ctx, nbase, 8, v); }
        gemm_regA<8, 2, 4>(sb, aph, alp, OFF_W2, lane, acc2);
        if (more) sts_chunk(smem, OFF_X0H, OFF_X0L, ctx.lb, ctx.part, 8, v);

        // ---- h2 = softplus(acc2 + b2); pack (reuse fragment regs) ----
        act_inplace(acc2, (const float*)(smem + OFF_BIAS) + 64, lane);
        pack_h(acc2, aph, alp);         // acc2 dead after this

        // ---- L3 (A from packed registers, N=32) ----
        float acc3[8][4];
        #pragma unroll
        for (int i = 0; i < 8; i++)
            #pragma unroll
            for (int q = 0; q < 4; q++) acc3[i][q] = 0.0f;
        gemm_regA<4, 0, 4>(sb, aph, alp, OFF_W3, lane, acc3);

        // ---- output: acc3 + b3 -> global ----
        {
            const float* bias = (const float*)(smem + OFF_BIAS) + 128;
            #pragma unroll
            for (int mt = 0; mt < 2; mt++)
            #pragma unroll
            for (int nt = 0; nt < 4; nt++) {
                const int col = nt * 8 + (lane & 3) * 2;
                const float bv0 = bias[col], bv1 = bias[col + 1];
                #pragma unroll
                for (int h = 0; h < 2; h++) {
                    const int row = m0 + mt * 16 + (lane >> 2) + h * 8;
                    const long long gb = base + row;
                    if (gb < n_bond) {
                        float2 o = make_float2(acc3[mt * 4 + nt][2 * h]     + bv0,
                                               acc3[mt * 4 + nt][2 * h + 1] + bv1);
                        *(float2*)(out + (size_t)gb * 32 + col) = o;
                    }
                }
            }
        }

        if (!more) break;
        tile = ntile; base = nbase;
        __syncthreads();   // X0 (next seg0) visible; X1 seg3 reads complete
    }
}

// ---------------------------------------------------------------------------
extern "C" void kernel_launch(void* const* d_in, const int* in_sizes, int n_in,
                              void* d_out, int out_size)
{
    const float* bond_feats   = (const float*)d_in[0];
    const float* atom_feats   = (const float*)d_in[1];
    const float* global_feats = (const float*)d_in[2];
    const void*  atom_idx     = d_in[3];
    const void*  global_idx   = d_in[4];
    const float* W1 = (const float*)d_in[5];
    const float* b1 = (const float*)d_in[6];
    const float* W2 = (const float*)d_in[7];
    const float* b2 = (const float*)d_in[8];
    const float* W3 = (const float*)d_in[9];
    const float* b3 = (const float*)d_in[10];
    float* out = (float*)d_out;

    const int n_bond = in_sizes[0] / 64;
    const long long ntiles = (n_bond + M_CTA - 1) / M_CTA;

    static int smCount = 0;
    if (!smCount) {
        cudaFuncSetAttribute(bond_mlp_mma,
                             cudaFuncAttributeMaxDynamicSharedMemorySize, SMEM_TOTAL);
        cudaDeviceGetAttribute(&smCount, cudaDevAttrMultiProcessorCount, 0);
        if (smCount <= 0) smCount = 148;
    }

    stage_weights<<<97, 256>>>(W1, b1, W2, b2, W3, b3, (const unsigned int*)atom_idx);

    const int grid = (int)((ntiles < smCount) ? ntiles : smCount);
    bond_mlp_mma<<<grid, TPB, SMEM_TOTAL>>>(
        bond_feats, atom_feats, global_feats, atom_idx, global_idx, out, n_bond);
}